// round 9
// baseline (speedup 1.0000x reference)
#include <cuda_runtime.h>
#include <cuda_bf16.h>
#include <cstdint>
#include <cstring>

// ---------------------------------------------------------------------------
// Problem constants
// ---------------------------------------------------------------------------
static constexpr int C      = 128;          // emb dim (GEMM K)
static constexpr int NCLS   = 128;          // classes (GEMM N)
static constexpr int HW     = 262144;       // spatial positions (GEMM M total)
static constexpr int K      = 131072;       // gathered rows
static constexpr int TILE_M = 128;
static constexpr int NTILES = HW / TILE_M;  // 2048
static constexpr int BCAP   = 16;           // bucket capacity (Poisson(0.5): overflow ~1e-21)
static constexpr int KCH    = 64;           // k-chunk (smem A staging)

// ---------------------------------------------------------------------------
// Device scratch (static — no runtime allocation)
// ---------------------------------------------------------------------------
__device__ int g_idx[K];                      // normalized int32 indices
__device__ int g_cnt[HW];                     // per-position multiplicity
__device__ int g_bucket[(size_t)HW * BCAP];   // inverted index (16 MB)
__device__ __align__(16) uint32_t g_WfHi[8192];  // W hi frags, lane-ordered
__device__ __align__(16) uint32_t g_WfLo[8192];  // W lo frags

// ---------------------------------------------------------------------------
// Warp MMA: m16n8k16, bf16 x bf16 -> fp32  (arch-portable HMMA path)
// ---------------------------------------------------------------------------
__device__ __forceinline__ void mma16816(float* c, const uint32_t* a,
                                         uint32_t b0, uint32_t b1) {
    asm volatile(
        "mma.sync.aligned.m16n8k16.row.col.f32.bf16.bf16.f32 "
        "{%0,%1,%2,%3}, {%4,%5,%6,%7}, {%8,%9}, {%0,%1,%2,%3};"
        : "+f"(c[0]), "+f"(c[1]), "+f"(c[2]), "+f"(c[3])
        : "r"(a[0]), "r"(a[1]), "r"(a[2]), "r"(a[3]), "r"(b0), "r"(b1));
}

__device__ __forceinline__ void pack_pair(float a0, float a1,
                                          uint32_t& hi, uint32_t& lo) {
    __nv_bfloat16 h0 = __float2bfloat16(a0);
    __nv_bfloat16 h1 = __float2bfloat16(a1);
    __nv_bfloat16 l0 = __float2bfloat16(a0 - __bfloat162float(h0));
    __nv_bfloat16 l1 = __float2bfloat16(a1 - __bfloat162float(h1));
    unsigned short h0b, h1b, l0b, l1b;
    memcpy(&h0b, &h0, 2); memcpy(&h1b, &h1, 2);
    memcpy(&l0b, &l0, 2); memcpy(&l1b, &l1, 2);
    hi = (uint32_t)h0b | ((uint32_t)h1b << 16);
    lo = (uint32_t)l0b | ((uint32_t)l1b << 16);
}

// ---------------------------------------------------------------------------
// Kernel 1: zero counters + normalize index dtype (int64-or-int32) to int32
// ---------------------------------------------------------------------------
__global__ void zero_convert_kernel(const void* __restrict__ raw) {
    int t = blockIdx.x * 256 + threadIdx.x;      // HW threads
    g_cnt[t] = 0;
    if (t < K) {
        const int* i32 = (const int*)raw;
        bool is64 = true;
#pragma unroll
        for (int j = 0; j < 32; j++)
            if (i32[2 * j + 1] != 0) is64 = false;
        g_idx[t] = is64 ? i32[2 * t] : i32[t];
    }
}

// ---------------------------------------------------------------------------
// Kernel 2: scatter k into fixed-capacity buckets
// ---------------------------------------------------------------------------
__global__ void scatter_kernel() {
    int k = blockIdx.x * 256 + threadIdx.x;
    int p = g_idx[k];
    int s = atomicAdd(&g_cnt[p], 1);
    if (s < BCAP) g_bucket[(size_t)p * BCAP + s] = k;
}

// ---------------------------------------------------------------------------
// Kernel 3: W -> bf16 hi/lo mma-fragment-ordered arrays.
// Entry t = ((kb*16+nb)*32 + lane)*2 + reg.
//   n = nb*8 + lane/4 ; k = kb*16 + (lane%4)*2 + reg*8 ; packs W[n][k],W[n][k+1]
// ---------------------------------------------------------------------------
__global__ void prepW_kernel(const float* __restrict__ W) {
    int t = blockIdx.x * 256 + threadIdx.x;      // 8192
    int r  = t & 1;
    int l  = (t >> 1) & 31;
    int f  = t >> 6;                              // kb*16+nb
    int kb = f >> 4, nb = f & 15;
    int n = nb * 8 + (l >> 2);
    int k = kb * 16 + (l & 3) * 2 + r * 8;
    uint32_t hi, lo;
    pack_pair(W[n * C + k], W[n * C + k + 1], hi, lo);
    g_WfHi[t] = hi;
    g_WfLo[t] = lo;
}

// ---------------------------------------------------------------------------
// Fused dense GEMM + softmax + inverted-gather epilogue.
// CTA: 128 positions x 128 classes; K in 2 chunks of 64 channels.
// 8 warps in a 2(m) x 4(n) grid: warp = 64 m x 32 n (4 mb x 4 nb mma tiles).
// A staged as pre-packed k-pair words: AHIP/ALOP[k2][m], stride 136
// (banks = 8t+q for frag reads -> conflict-free, zero unpack ALU).
// 3-pass bf16 hi/lo split, fp32 accum. Cross-warp softmax via 2 smem buffers.
// ---------------------------------------------------------------------------
static constexpr int ASTR    = 136;                 // uint32 stride per k2 row
static constexpr int SM_AHI  = 0;                   // 32*136*4 = 17408
static constexpr int SM_ALO  = 17408;               // 17408 -> 34816
static constexpr int SM_WHI  = 34816;               // 32768 -> 67584
static constexpr int SM_WLO  = 67584;               // 32768 -> 100352
static constexpr int SM_BIAS = 100352;              // 512   -> 100864
static constexpr int SM_RED1 = 100864;              // 2048  -> 102912
static constexpr int SM_RED2 = 102912;              // 2048  -> 104960
static constexpr int SM_TOTAL = 104960;

__global__ void __launch_bounds__(256, 2)
gemm_kernel(const float* __restrict__ gc,
            const float* __restrict__ bias,
            float* __restrict__ out) {
    extern __shared__ unsigned char smem[];
    uint32_t* AHIP = (uint32_t*)(smem + SM_AHI);
    uint32_t* ALOP = (uint32_t*)(smem + SM_ALO);
    const uint2* WH = (const uint2*)(smem + SM_WHI);
    const uint2* WL = (const uint2*)(smem + SM_WLO);
    float* bs   = (float*)(smem + SM_BIAS);
    float* red1 = (float*)(smem + SM_RED1);
    float* red2 = (float*)(smem + SM_RED2);

    int tid  = threadIdx.x;
    int lane = tid & 31;
    int warp = tid >> 5;
    int p0   = blockIdx.x * TILE_M;
    int q    = lane >> 2;                // row within octet
    int t    = lane & 3;                 // quad thread

    // Stage W fragment arrays + bias (covered by first __syncthreads)
    {
        const int4* shi = (const int4*)g_WfHi;           // 2048 int4
        const int4* slo = (const int4*)g_WfLo;
        int4* dhi = (int4*)(smem + SM_WHI);
        int4* dlo = (int4*)(smem + SM_WLO);
#pragma unroll
        for (int i = 0; i < 8; i++) {
            dhi[tid + i * 256] = shi[tid + i * 256];
            dlo[tid + i * 256] = slo[tid + i * 256];
        }
        if (tid < NCLS) bs[tid] = bias[tid];
    }

    int mwarp = (warp >> 2) * 64;        // m-group base (0 or 64)
    int ng4   = (warp & 3) * 4;          // first global nb of this warp

    float acc[4][4][4];                  // [mb][nb][reg]
#pragma unroll
    for (int mb = 0; mb < 4; mb++)
#pragma unroll
        for (int nb = 0; nb < 4; nb++)
#pragma unroll
            for (int j = 0; j < 4; j++) acc[mb][nb][j] = 0.0f;

#pragma unroll
    for (int kh = 0; kh < 2; kh++) {
        // ---- Stage A chunk: warp handles 4 k2 rows (channel pairs) ----
        // Lane t covers m = lane + 32j: LDG coalesced, STS conflict-free.
#pragma unroll
        for (int k2i = 0; k2i < 4; k2i++) {
            int k2 = warp * 4 + k2i;
            const float* s0 = gc + (size_t)(kh * KCH + 2 * k2) * HW + p0 + lane;
            const float* s1 = s0 + HW;
            uint32_t* dh = AHIP + k2 * ASTR + lane;
            uint32_t* dl = ALOP + k2 * ASTR + lane;
#pragma unroll
            for (int j = 0; j < 4; j++) {
                uint32_t hi, lo;
                pack_pair(s0[32 * j], s1[32 * j], hi, lo);
                dh[32 * j] = hi;
                dl[32 * j] = lo;
            }
        }
        __syncthreads();

        // ---- MMA: 4 k16-blocks in this chunk ----
#pragma unroll
        for (int kb = 0; kb < 4; kb++) {
            int r0 = (kb * 8 + t) * ASTR;        // k2 row (low k-half)
            int r1 = r0 + 4 * ASTR;              // high k-half
            uint32_t ahi[4][4], alo[4][4];
#pragma unroll
            for (int mb = 0; mb < 4; mb++) {
                int m = mwarp + mb * 16 + q;
                ahi[mb][0] = AHIP[r0 + m];
                ahi[mb][1] = AHIP[r0 + m + 8];
                ahi[mb][2] = AHIP[r1 + m];
                ahi[mb][3] = AHIP[r1 + m + 8];
                alo[mb][0] = ALOP[r0 + m];
                alo[mb][1] = ALOP[r0 + m + 8];
                alo[mb][2] = ALOP[r1 + m];
                alo[mb][3] = ALOP[r1 + m + 8];
            }
            int kbg = kh * 4 + kb;
#pragma unroll
            for (int nb = 0; nb < 4; nb++) {
                uint2 wh = WH[(kbg * 16 + ng4 + nb) * 32 + lane];
                uint2 wl = WL[(kbg * 16 + ng4 + nb) * 32 + lane];
#pragma unroll
                for (int mb = 0; mb < 4; mb++) {
                    mma16816(acc[mb][nb], ahi[mb], wh.x, wh.y);  // Ahi*Bhi
                    mma16816(acc[mb][nb], ahi[mb], wl.x, wl.y);  // Ahi*Blo
                    mma16816(acc[mb][nb], alo[mb], wh.x, wh.y);  // Alo*Bhi
                }
            }
        }
        __syncthreads();
    }

    // ---- Bias add ----
#pragma unroll
    for (int nb = 0; nb < 4; nb++) {
        float b0 = bs[(ng4 + nb) * 8 + t * 2];
        float b1 = bs[(ng4 + nb) * 8 + t * 2 + 1];
#pragma unroll
        for (int mb = 0; mb < 4; mb++) {
            acc[mb][nb][0] += b0; acc[mb][nb][1] += b1;
            acc[mb][nb][2] += b0; acc[mb][nb][3] += b1;
        }
    }

    // ---- Softmax: quad-reduce -> cross-warp (4 n-groups) via smem ----
    int ng = warp & 3;
    float pm[4][2];
#pragma unroll
    for (int mb = 0; mb < 4; mb++) {
        float a = -3.4e38f, b = -3.4e38f;
#pragma unroll
        for (int nb = 0; nb < 4; nb++) {
            a = fmaxf(a, fmaxf(acc[mb][nb][0], acc[mb][nb][1]));
            b = fmaxf(b, fmaxf(acc[mb][nb][2], acc[mb][nb][3]));
        }
#pragma unroll
        for (int o = 1; o <= 2; o <<= 1) {
            a = fmaxf(a, __shfl_xor_sync(0xffffffffu, a, o));
            b = fmaxf(b, __shfl_xor_sync(0xffffffffu, b, o));
        }
        pm[mb][0] = a; pm[mb][1] = b;
    }
    if (t == 0) {
#pragma unroll
        for (int mb = 0; mb < 4; mb++) {
            int row = mwarp + mb * 16 + q;
            red1[ng * 128 + row]     = pm[mb][0];
            red1[ng * 128 + row + 8] = pm[mb][1];
        }
    }
    __syncthreads();

    float ps[4][2];
#pragma unroll
    for (int mb = 0; mb < 4; mb++) {
        int row = mwarp + mb * 16 + q;
        float gm0 = fmaxf(fmaxf(red1[row], red1[128 + row]),
                          fmaxf(red1[256 + row], red1[384 + row]));
        float gm1 = fmaxf(fmaxf(red1[row + 8], red1[128 + row + 8]),
                          fmaxf(red1[256 + row + 8], red1[384 + row + 8]));
        float sa = 0.0f, sb = 0.0f;
#pragma unroll
        for (int nb = 0; nb < 4; nb++) {
            acc[mb][nb][0] = __expf(acc[mb][nb][0] - gm0);
            acc[mb][nb][1] = __expf(acc[mb][nb][1] - gm0);
            acc[mb][nb][2] = __expf(acc[mb][nb][2] - gm1);
            acc[mb][nb][3] = __expf(acc[mb][nb][3] - gm1);
            sa += acc[mb][nb][0] + acc[mb][nb][1];
            sb += acc[mb][nb][2] + acc[mb][nb][3];
        }
#pragma unroll
        for (int o = 1; o <= 2; o <<= 1) {
            sa += __shfl_xor_sync(0xffffffffu, sa, o);
            sb += __shfl_xor_sync(0xffffffffu, sb, o);
        }
        ps[mb][0] = sa; ps[mb][1] = sb;
    }
    if (t == 0) {
#pragma unroll
        for (int mb = 0; mb < 4; mb++) {
            int row = mwarp + mb * 16 + q;
            red2[ng * 128 + row]     = ps[mb][0];
            red2[ng * 128 + row + 8] = ps[mb][1];
        }
    }
    __syncthreads();

    // ---- Normalize + inverted-gather writes ----
#pragma unroll
    for (int mb = 0; mb < 4; mb++) {
        int row = mwarp + mb * 16 + q;
        float inv0 = 1.0f / (red2[row] + red2[128 + row] +
                             red2[256 + row] + red2[384 + row]);
        float inv1 = 1.0f / (red2[row + 8] + red2[128 + row + 8] +
                             red2[256 + row + 8] + red2[384 + row + 8]);
#pragma unroll
        for (int nb = 0; nb < 4; nb++) {
            acc[mb][nb][0] *= inv0; acc[mb][nb][1] *= inv0;
            acc[mb][nb][2] *= inv1; acc[mb][nb][3] *= inv1;
        }
        // row (low octet)
        {
            int p = p0 + row;
            int n = min(g_cnt[p], BCAP);
            for (int j = 0; j < n; j++) {
                int k = g_bucket[(size_t)p * BCAP + j];
                float2* o = (float2*)(out + (size_t)k * NCLS);
#pragma unroll
                for (int nb = 0; nb < 4; nb++)
                    o[(ng4 + nb) * 4 + t] =
                        make_float2(acc[mb][nb][0], acc[mb][nb][1]);
            }
        }
        // row + 8 (high octet)
        {
            int p = p0 + row + 8;
            int n = min(g_cnt[p], BCAP);
            for (int j = 0; j < n; j++) {
                int k = g_bucket[(size_t)p * BCAP + j];
                float2* o = (float2*)(out + (size_t)k * NCLS);
#pragma unroll
                for (int nb = 0; nb < 4; nb++)
                    o[(ng4 + nb) * 4 + t] =
                        make_float2(acc[mb][nb][2], acc[mb][nb][3]);
            }
        }
    }
}

// ---------------------------------------------------------------------------
// Launch
// ---------------------------------------------------------------------------
extern "C" void kernel_launch(void* const* d_in, const int* in_sizes, int n_in,
                              void* d_out, int out_size) {
    const float* gc   = (const float*)d_in[0];   // [1,128,512,512] f32
    const void*  cmap = d_in[1];                 // [1,131072] int64/int32
    const float* Wc   = (const float*)d_in[2];   // [128,128] f32
    const float* bc   = (const float*)d_in[3];   // [128] f32
    float*       out  = (float*)d_out;           // [131072,128] f32

    zero_convert_kernel<<<HW / 256, 256>>>(cmap);
    scatter_kernel<<<K / 256, 256>>>();
    prepW_kernel<<<32, 256>>>(Wc);

    cudaFuncSetAttribute(gemm_kernel,
                         cudaFuncAttributeMaxDynamicSharedMemorySize, SM_TOTAL);
    gemm_kernel<<<NTILES, 256, SM_TOTAL>>>(gc, bc, out);
}

// round 11
// speedup vs baseline: 1.1294x; 1.1294x over previous
#include <cuda_runtime.h>
#include <cuda_bf16.h>
#include <cstdint>
#include <cstring>

// ---------------------------------------------------------------------------
// Problem constants
// ---------------------------------------------------------------------------
static constexpr int C      = 128;          // emb dim (GEMM K)
static constexpr int NCLS   = 128;          // classes (GEMM N)
static constexpr int HW     = 262144;       // spatial positions (GEMM M total)
static constexpr int K      = 131072;       // gathered rows
static constexpr int TILE_M = 128;
static constexpr int NTILES = HW / TILE_M;  // 2048
static constexpr int BCAP   = 16;           // bucket capacity (Poisson(0.5): overflow ~1e-21)
static constexpr int KCH    = 32;           // k-chunk channels (4 chunks, double-buffered)
static constexpr int NCHUNK = C / KCH;      // 4

// ---------------------------------------------------------------------------
// Device scratch (static — no runtime allocation)
// ---------------------------------------------------------------------------
__device__ int g_idx[K];                      // normalized int32 indices
__device__ int g_cnt[HW];                     // per-position multiplicity
__device__ int g_bucket[(size_t)HW * BCAP];   // inverted index (16 MB)
__device__ __align__(16) uint32_t g_WfHi[8192];  // W hi frags, lane-ordered
__device__ __align__(16) uint32_t g_WfLo[8192];  // W lo frags

// ---------------------------------------------------------------------------
// Warp MMA: m16n8k16, bf16 x bf16 -> fp32  (arch-portable HMMA path)
// ---------------------------------------------------------------------------
__device__ __forceinline__ void mma16816(float* c, const uint32_t* a,
                                         uint32_t b0, uint32_t b1) {
    asm volatile(
        "mma.sync.aligned.m16n8k16.row.col.f32.bf16.bf16.f32 "
        "{%0,%1,%2,%3}, {%4,%5,%6,%7}, {%8,%9}, {%0,%1,%2,%3};"
        : "+f"(c[0]), "+f"(c[1]), "+f"(c[2]), "+f"(c[3])
        : "r"(a[0]), "r"(a[1]), "r"(a[2]), "r"(a[3]), "r"(b0), "r"(b1));
}

__device__ __forceinline__ void pack_pair(float a0, float a1,
                                          uint32_t& hi, uint32_t& lo) {
    __nv_bfloat16 h0 = __float2bfloat16(a0);
    __nv_bfloat16 h1 = __float2bfloat16(a1);
    __nv_bfloat16 l0 = __float2bfloat16(a0 - __bfloat162float(h0));
    __nv_bfloat16 l1 = __float2bfloat16(a1 - __bfloat162float(h1));
    unsigned short h0b, h1b, l0b, l1b;
    memcpy(&h0b, &h0, 2); memcpy(&h1b, &h1, 2);
    memcpy(&l0b, &l0, 2); memcpy(&l1b, &l1, 2);
    hi = (uint32_t)h0b | ((uint32_t)h1b << 16);
    lo = (uint32_t)l0b | ((uint32_t)l1b << 16);
}

__device__ __forceinline__ uint32_t smem_u32(const void* p) {
    uint32_t a;
    asm("{ .reg .u64 t; cvta.to.shared.u64 t, %1; cvt.u32.u64 %0, t; }"
        : "=r"(a) : "l"(p));
    return a;
}

#define CP_ASYNC16(dst, src) \
    asm volatile("cp.async.cg.shared.global [%0], [%1], 16;" :: "r"(dst), "l"(src))
#define CP_COMMIT() asm volatile("cp.async.commit_group;" ::: "memory")
#define CP_WAIT1()  asm volatile("cp.async.wait_group 1;" ::: "memory")
#define CP_WAIT0()  asm volatile("cp.async.wait_group 0;" ::: "memory")

// ---------------------------------------------------------------------------
// Kernel 1: zero counters + normalize index dtype (int64-or-int32) to int32
// ---------------------------------------------------------------------------
__global__ void zero_convert_kernel(const void* __restrict__ raw) {
    int t = blockIdx.x * 256 + threadIdx.x;      // HW threads
    g_cnt[t] = 0;
    if (t < K) {
        const int* i32 = (const int*)raw;
        bool is64 = true;
#pragma unroll
        for (int j = 0; j < 32; j++)
            if (i32[2 * j + 1] != 0) is64 = false;
        g_idx[t] = is64 ? i32[2 * t] : i32[t];
    }
}

// ---------------------------------------------------------------------------
// Kernel 2: scatter k into fixed-capacity buckets
// ---------------------------------------------------------------------------
__global__ void scatter_kernel() {
    int k = blockIdx.x * 256 + threadIdx.x;
    int p = g_idx[k];
    int s = atomicAdd(&g_cnt[p], 1);
    if (s < BCAP) g_bucket[(size_t)p * BCAP + s] = k;
}

// ---------------------------------------------------------------------------
// Kernel 3: W -> bf16 hi/lo mma-fragment-ordered arrays.
// Entry t = ((kb*16+nb)*32 + lane)*2 + reg.
//   n = nb*8 + lane/4 ; k = kb*16 + (lane%4)*2 + reg*8 ; packs W[n][k],W[n][k+1]
// ---------------------------------------------------------------------------
__global__ void prepW_kernel(const float* __restrict__ W) {
    int t = blockIdx.x * 256 + threadIdx.x;      // 8192
    int r  = t & 1;
    int l  = (t >> 1) & 31;
    int f  = t >> 6;                              // kb*16+nb
    int kb = f >> 4, nb = f & 15;
    int n = nb * 8 + (l >> 2);
    int k = kb * 16 + (l & 3) * 2 + r * 8;
    uint32_t hi, lo;
    pack_pair(W[n * C + k], W[n * C + k + 1], hi, lo);
    g_WfHi[t] = hi;
    g_WfLo[t] = lo;
}

// ---------------------------------------------------------------------------
// Fused dense GEMM + softmax + inverted-gather epilogue.
// R7 structure (8 warps x (16 m x 128 n), known 106.7us) + cp.async
// double-buffered A staging: 4 chunks of 32 channels, fp32 in smem,
// hi/lo conversion folded into the fragment load (bit-identical math).
// smem: A 2x32x132 f32 (33.8KB) + W frags (64KB) + bias = 99.8KB => 2 CTA/SM.
// ---------------------------------------------------------------------------
static constexpr int ASTR    = 132;                 // f32 stride per channel row
static constexpr int ABUFSZ  = KCH * ASTR;          // 4224 floats per buffer
static constexpr int SM_A    = 0;                   // 2*4224*4 = 33792
static constexpr int SM_WHI  = 33792;               // 32768 -> 66560
static constexpr int SM_WLO  = 66560;               // 32768 -> 99328
static constexpr int SM_BIAS = 99328;               // 512   -> 99840
static constexpr int SM_TOTAL = 99840;

__global__ void __launch_bounds__(256, 2)
gemm_kernel(const float* __restrict__ gc,
            const float* __restrict__ bias,
            float* __restrict__ out) {
    extern __shared__ unsigned char smem[];
    float* ABUF = (float*)(smem + SM_A);
    const uint2* WH = (const uint2*)(smem + SM_WHI);
    const uint2* WL = (const uint2*)(smem + SM_WLO);
    float* bs = (float*)(smem + SM_BIAS);

    int tid  = threadIdx.x;
    int lane = tid & 31;
    int warp = tid >> 5;
    int p0   = blockIdx.x * TILE_M;

    uint32_t a_smem = smem_u32(ABUF);

    // Stage W fragment arrays + bias (covered by first __syncthreads)
    {
        const int4* shi = (const int4*)g_WfHi;           // 2048 int4
        const int4* slo = (const int4*)g_WfLo;
        int4* dhi = (int4*)(smem + SM_WHI);
        int4* dlo = (int4*)(smem + SM_WLO);
#pragma unroll
        for (int i = 0; i < 8; i++) {
            dhi[tid + i * 256] = shi[tid + i * 256];
            dlo[tid + i * 256] = slo[tid + i * 256];
        }
        if (tid < NCLS) bs[tid] = bias[tid];
    }

    int mA = warp * 16 + (lane >> 2);
    int mB = mA + 8;

    float acc[16][4];
#pragma unroll
    for (int nb = 0; nb < 16; nb++)
#pragma unroll
        for (int j = 0; j < 4; j++) acc[nb][j] = 0.0f;

    // ---- cp.async staging helper (inlined): chunk ch -> buffer buf ----
    // 1024 float4 per chunk, 4 per thread; LDG coalesced 512B segments.
#define STAGE_CHUNK(ch, buf)                                                   \
    do {                                                                       \
        _Pragma("unroll")                                                      \
        for (int i = 0; i < 4; i++) {                                          \
            int e4 = tid + i * 256;                                            \
            int c  = e4 >> 5;                                                  \
            int m  = (e4 & 31) * 4;                                            \
            const float* src = gc + (size_t)((ch) * KCH + c) * HW + p0 + m;    \
            uint32_t dst = a_smem + (uint32_t)(((buf) * ABUFSZ) +              \
                                               c * ASTR + m) * 4u;             \
            CP_ASYNC16(dst, src);                                              \
        }                                                                      \
        CP_COMMIT();                                                           \
    } while (0)

    STAGE_CHUNK(0, 0);

#pragma unroll
    for (int ch = 0; ch < NCHUNK; ch++) {
        if (ch + 1 < NCHUNK) STAGE_CHUNK(ch + 1, (ch + 1) & 1);
        if (ch + 1 < NCHUNK) CP_WAIT1(); else CP_WAIT0();
        __syncthreads();

        const float* A = ABUF + (ch & 1) * ABUFSZ;

        // 2 k16-blocks per chunk
#pragma unroll
        for (int kb = 0; kb < 2; kb++) {
            int k0 = kb * 16 + (lane & 3) * 2;
            float f0 = A[(k0    ) * ASTR + mA];
            float f1 = A[(k0 + 1) * ASTR + mA];
            float f2 = A[(k0 + 8) * ASTR + mA];
            float f3 = A[(k0 + 9) * ASTR + mA];
            float g0 = A[(k0    ) * ASTR + mB];
            float g1 = A[(k0 + 1) * ASTR + mB];
            float g2 = A[(k0 + 8) * ASTR + mB];
            float g3 = A[(k0 + 9) * ASTR + mB];
            uint32_t ahi[4], alo[4];
            pack_pair(f0, f1, ahi[0], alo[0]);
            pack_pair(g0, g1, ahi[1], alo[1]);
            pack_pair(f2, f3, ahi[2], alo[2]);
            pack_pair(g2, g3, ahi[3], alo[3]);

            int kbg = ch * 2 + kb;
#pragma unroll
            for (int nb = 0; nb < 16; nb++) {
                uint2 wh = WH[(kbg * 16 + nb) * 32 + lane];
                uint2 wl = WL[(kbg * 16 + nb) * 32 + lane];
                mma16816(acc[nb], ahi, wh.x, wh.y);   // Ahi * Bhi
                mma16816(acc[nb], ahi, wl.x, wl.y);   // Ahi * Blo
                mma16816(acc[nb], alo, wh.x, wh.y);   // Alo * Bhi
            }
        }
        __syncthreads();
    }
#undef STAGE_CHUNK

    // Bias add. Lane owns cols nb*8 + (lane%4)*2 + {0,1}; rows mA (c0,c1), mB (c2,c3)
    int col0 = (lane & 3) * 2;
#pragma unroll
    for (int nb = 0; nb < 16; nb++) {
        float b0 = bs[nb * 8 + col0];
        float b1 = bs[nb * 8 + col0 + 1];
        acc[nb][0] += b0; acc[nb][1] += b1;
        acc[nb][2] += b0; acc[nb][3] += b1;
    }

    // Softmax per row; reduction across the 4 lanes of each quad
    float mxA = -3.4e38f, mxB = -3.4e38f;
#pragma unroll
    for (int nb = 0; nb < 16; nb++) {
        mxA = fmaxf(mxA, fmaxf(acc[nb][0], acc[nb][1]));
        mxB = fmaxf(mxB, fmaxf(acc[nb][2], acc[nb][3]));
    }
#pragma unroll
    for (int o = 1; o <= 2; o <<= 1) {
        mxA = fmaxf(mxA, __shfl_xor_sync(0xffffffffu, mxA, o));
        mxB = fmaxf(mxB, __shfl_xor_sync(0xffffffffu, mxB, o));
    }
    float sA = 0.0f, sB = 0.0f;
#pragma unroll
    for (int nb = 0; nb < 16; nb++) {
        acc[nb][0] = __expf(acc[nb][0] - mxA);
        acc[nb][1] = __expf(acc[nb][1] - mxA);
        acc[nb][2] = __expf(acc[nb][2] - mxB);
        acc[nb][3] = __expf(acc[nb][3] - mxB);
        sA += acc[nb][0] + acc[nb][1];
        sB += acc[nb][2] + acc[nb][3];
    }
#pragma unroll
    for (int o = 1; o <= 2; o <<= 1) {
        sA += __shfl_xor_sync(0xffffffffu, sA, o);
        sB += __shfl_xor_sync(0xffffffffu, sB, o);
    }
    float invA = 1.0f / sA, invB = 1.0f / sB;
#pragma unroll
    for (int nb = 0; nb < 16; nb++) {
        acc[nb][0] *= invA; acc[nb][1] *= invA;
        acc[nb][2] *= invB; acc[nb][3] *= invB;
    }

    // Inverted gather: write each row to every k in its bucket (float2 stores)
    {
        int pA = p0 + mA;
        int nA = min(g_cnt[pA], BCAP);
        for (int j = 0; j < nA; j++) {
            int k = g_bucket[(size_t)pA * BCAP + j];
            float2* o = (float2*)(out + (size_t)k * NCLS);
#pragma unroll
            for (int nb = 0; nb < 16; nb++)
                o[nb * 4 + (lane & 3)] = make_float2(acc[nb][0], acc[nb][1]);
        }
        int pB = p0 + mB;
        int nB = min(g_cnt[pB], BCAP);
        for (int j = 0; j < nB; j++) {
            int k = g_bucket[(size_t)pB * BCAP + j];
            float2* o = (float2*)(out + (size_t)k * NCLS);
#pragma unroll
            for (int nb = 0; nb < 16; nb++)
                o[nb * 4 + (lane & 3)] = make_float2(acc[nb][2], acc[nb][3]);
        }
    }
}

// ---------------------------------------------------------------------------
// Launch
// ---------------------------------------------------------------------------
extern "C" void kernel_launch(void* const* d_in, const int* in_sizes, int n_in,
                              void* d_out, int out_size) {
    const float* gc   = (const float*)d_in[0];   // [1,128,512,512] f32
    const void*  cmap = d_in[1];                 // [1,131072] int64/int32
    const float* Wc   = (const float*)d_in[2];   // [128,128] f32
    const float* bc   = (const float*)d_in[3];   // [128] f32
    float*       out  = (float*)d_out;           // [131072,128] f32

    zero_convert_kernel<<<HW / 256, 256>>>(cmap);
    scatter_kernel<<<K / 256, 256>>>();
    prepW_kernel<<<32, 256>>>(Wc);

    cudaFuncSetAttribute(gemm_kernel,
                         cudaFuncAttributeMaxDynamicSharedMemorySize, SM_TOTAL);
    gemm_kernel<<<NTILES, 256, SM_TOTAL>>>(gc, bc, out);
}

// round 12
// speedup vs baseline: 1.1458x; 1.0145x over previous
#include <cuda_runtime.h>
#include <cuda_bf16.h>
#include <cstdint>
#include <cstring>

// ---------------------------------------------------------------------------
// Problem constants
// ---------------------------------------------------------------------------
static constexpr int C      = 128;          // emb dim (GEMM K)
static constexpr int NCLS   = 128;          // classes (GEMM N)
static constexpr int HW     = 262144;       // spatial positions (GEMM M total)
static constexpr int K      = 131072;       // gathered rows
static constexpr int TILE_M = 128;
static constexpr int NTILES = HW / TILE_M;  // 2048
static constexpr int BCAP   = 16;           // bucket capacity (Poisson(0.5): overflow ~1e-21)
static constexpr int KCH    = 64;           // k-chunk (smem A staging)

// ---------------------------------------------------------------------------
// Device scratch (static — no runtime allocation)
// ---------------------------------------------------------------------------
__device__ int g_idx[K];                      // normalized int32 indices
__device__ int g_cnt[HW];                     // per-position multiplicity
__device__ int g_bucket[(size_t)HW * BCAP];   // inverted index (16 MB)
__device__ __align__(16) uint32_t g_WfHi[8192];  // W hi frags, lane-ordered
__device__ __align__(16) uint32_t g_WfLo[8192];  // W lo frags

// ---------------------------------------------------------------------------
// Warp MMA: m16n8k16, bf16 x bf16 -> fp32  (arch-portable HMMA path)
// ---------------------------------------------------------------------------
__device__ __forceinline__ void mma16816(float* c, const uint32_t* a,
                                         uint32_t b0, uint32_t b1) {
    asm volatile(
        "mma.sync.aligned.m16n8k16.row.col.f32.bf16.bf16.f32 "
        "{%0,%1,%2,%3}, {%4,%5,%6,%7}, {%8,%9}, {%0,%1,%2,%3};"
        : "+f"(c[0]), "+f"(c[1]), "+f"(c[2]), "+f"(c[3])
        : "r"(a[0]), "r"(a[1]), "r"(a[2]), "r"(a[3]), "r"(b0), "r"(b1));
}

__device__ __forceinline__ uint32_t pack_hilo(float a) {
    // low 16 bits: bf16(a) ; high 16 bits: bf16(a - bf16(a))
    __nv_bfloat16 h = __float2bfloat16(a);
    float r = a - __bfloat162float(h);
    __nv_bfloat16 l = __float2bfloat16(r);
    unsigned short hb, lb;
    memcpy(&hb, &h, 2);
    memcpy(&lb, &l, 2);
    return (uint32_t)hb | ((uint32_t)lb << 16);
}

__device__ __forceinline__ void pack_pair(float a0, float a1,
                                          uint32_t& hi, uint32_t& lo) {
    __nv_bfloat16 h0 = __float2bfloat16(a0);
    __nv_bfloat16 h1 = __float2bfloat16(a1);
    __nv_bfloat16 l0 = __float2bfloat16(a0 - __bfloat162float(h0));
    __nv_bfloat16 l1 = __float2bfloat16(a1 - __bfloat162float(h1));
    unsigned short h0b, h1b, l0b, l1b;
    memcpy(&h0b, &h0, 2); memcpy(&h1b, &h1, 2);
    memcpy(&l0b, &l0, 2); memcpy(&l1b, &l1, 2);
    hi = (uint32_t)h0b | ((uint32_t)h1b << 16);
    lo = (uint32_t)l0b | ((uint32_t)l1b << 16);
}

// ---------------------------------------------------------------------------
// Kernel 1: zero counters + normalize index dtype (int64-or-int32) to int32
// ---------------------------------------------------------------------------
__global__ void zero_convert_kernel(const void* __restrict__ raw) {
    int t = blockIdx.x * 256 + threadIdx.x;      // HW threads
    g_cnt[t] = 0;
    if (t < K) {
        const int* i32 = (const int*)raw;
        bool is64 = true;
#pragma unroll
        for (int j = 0; j < 32; j++)
            if (i32[2 * j + 1] != 0) is64 = false;
        g_idx[t] = is64 ? i32[2 * t] : i32[t];
    }
}

// ---------------------------------------------------------------------------
// Kernel 2: scatter k into fixed-capacity buckets
// ---------------------------------------------------------------------------
__global__ void scatter_kernel() {
    int k = blockIdx.x * 256 + threadIdx.x;
    int p = g_idx[k];
    int s = atomicAdd(&g_cnt[p], 1);
    if (s < BCAP) g_bucket[(size_t)p * BCAP + s] = k;
}

// ---------------------------------------------------------------------------
// Kernel 3: W -> bf16 hi/lo mma-fragment-ordered arrays.
// Entry t = ((kb*16+nb)*32 + lane)*2 + reg.
//   n = nb*8 + lane/4 ; k = kb*16 + (lane%4)*2 + reg*8 ; packs W[n][k],W[n][k+1]
// ---------------------------------------------------------------------------
__global__ void prepW_kernel(const float* __restrict__ W) {
    int t = blockIdx.x * 256 + threadIdx.x;      // 8192
    int r  = t & 1;
    int l  = (t >> 1) & 31;
    int f  = t >> 6;                              // kb*16+nb
    int kb = f >> 4, nb = f & 15;
    int n = nb * 8 + (l >> 2);
    int k = kb * 16 + (l & 3) * 2 + r * 8;
    uint32_t hi, lo;
    pack_pair(W[n * C + k], W[n * C + k + 1], hi, lo);
    g_WfHi[t] = hi;
    g_WfLo[t] = lo;
}

// ---------------------------------------------------------------------------
// Fused dense GEMM + softmax + inverted-gather epilogue.
// R7 mechanics (pre-packed A words, 2x64-ch single-buffered chunks, bit-op
// fragment recombination) with 4 warps x (32 m x 128 n): each warp owns two
// m16 mma tiles, halving per-CTA W-fragment smem reads (512KB -> 256KB).
// Block = 128 threads, __launch_bounds__(128,2): regs free up to ~255,
// smem 99.8KB => 2 CTAs/SM.
// ---------------------------------------------------------------------------
static constexpr int ASTR    = 132;                 // packed-word stride per k row
static constexpr int SM_AS   = 0;                   // 64*132*4 = 33792
static constexpr int SM_WHI  = 33792;               // 32768 -> 66560
static constexpr int SM_WLO  = 66560;               // 32768 -> 99328
static constexpr int SM_BIAS = 99328;               // 512   -> 99840
static constexpr int SM_TOTAL = 99840;

__global__ void __launch_bounds__(128, 2)
gemm_kernel(const float* __restrict__ gc,
            const float* __restrict__ bias,
            float* __restrict__ out) {
    extern __shared__ unsigned char smem[];
    uint32_t* AS = (uint32_t*)(smem + SM_AS);
    const uint2* WH = (const uint2*)(smem + SM_WHI);
    const uint2* WL = (const uint2*)(smem + SM_WLO);
    float* bs = (float*)(smem + SM_BIAS);

    int tid  = threadIdx.x;
    int lane = tid & 31;
    int warp = tid >> 5;                 // 0..3
    int p0   = blockIdx.x * TILE_M;
    int q    = lane >> 2;                // 0..7
    int t    = lane & 3;                 // 0..3

    // Stage W fragment arrays + bias (covered by first __syncthreads)
    {
        const int4* shi = (const int4*)g_WfHi;           // 2048 int4 each
        const int4* slo = (const int4*)g_WfLo;
        int4* dhi = (int4*)(smem + SM_WHI);
        int4* dlo = (int4*)(smem + SM_WLO);
#pragma unroll
        for (int i = 0; i < 16; i++) {
            dhi[tid + i * 128] = shi[tid + i * 128];
            dlo[tid + i * 128] = slo[tid + i * 128];
        }
        if (tid < NCLS) bs[tid] = bias[tid];
    }

    int wb = warp * 32;                  // warp m-base (2 mma tiles: wb, wb+16)

    float acc[2][16][4];                 // [mb][nb][reg]
#pragma unroll
    for (int mb = 0; mb < 2; mb++)
#pragma unroll
        for (int nb = 0; nb < 16; nb++)
#pragma unroll
            for (int j = 0; j < 4; j++) acc[mb][nb][j] = 0.0f;

#pragma unroll
    for (int kh = 0; kh < 2; kh++) {
        // ---- Stage A chunk: channels [kh*64, kh*64+64), float4 coalesced ----
#pragma unroll
        for (int i = 0; i < 16; i++) {
            int e4 = tid + i * 128;                      // 2048 float4
            int c  = e4 >> 5;                            // 0..63
            int m  = (e4 & 31) * 4;
            float4 v = *(const float4*)(gc + (size_t)(kh * KCH + c) * HW + p0 + m);
            uint32_t* dst = AS + c * ASTR + m;
            dst[0] = pack_hilo(v.x);
            dst[1] = pack_hilo(v.y);
            dst[2] = pack_hilo(v.z);
            dst[3] = pack_hilo(v.w);
        }
        __syncthreads();

        // ---- MMA: 4 k16-blocks in this chunk ----
#pragma unroll
        for (int kb = 0; kb < 4; kb++) {
            int k0 = kb * 16 + t * 2;
            uint32_t ahi[2][4], alo[2][4];
#pragma unroll
            for (int mb = 0; mb < 2; mb++) {
                int mlo = wb + mb * 16 + q;              // rows q, q+8 of tile
                uint32_t u0 = AS[(k0    ) * ASTR + mlo];
                uint32_t u1 = AS[(k0 + 1) * ASTR + mlo];
                uint32_t u2 = AS[(k0 + 8) * ASTR + mlo];
                uint32_t u3 = AS[(k0 + 9) * ASTR + mlo];
                uint32_t v0 = AS[(k0    ) * ASTR + mlo + 8];
                uint32_t v1 = AS[(k0 + 1) * ASTR + mlo + 8];
                uint32_t v2 = AS[(k0 + 8) * ASTR + mlo + 8];
                uint32_t v3 = AS[(k0 + 9) * ASTR + mlo + 8];
                ahi[mb][0] = (u0 & 0xffffu) | (u1 << 16);
                alo[mb][0] = (u0 >> 16)     | (u1 & 0xffff0000u);
                ahi[mb][1] = (v0 & 0xffffu) | (v1 << 16);
                alo[mb][1] = (v0 >> 16)     | (v1 & 0xffff0000u);
                ahi[mb][2] = (u2 & 0xffffu) | (u3 << 16);
                alo[mb][2] = (u2 >> 16)     | (u3 & 0xffff0000u);
                ahi[mb][3] = (v2 & 0xffffu) | (v3 << 16);
                alo[mb][3] = (v2 >> 16)     | (v3 & 0xffff0000u);
            }

            int kbg = kh * 4 + kb;
#pragma unroll
            for (int nb = 0; nb < 16; nb++) {
                uint2 wh = WH[(kbg * 16 + nb) * 32 + lane];
                uint2 wl = WL[(kbg * 16 + nb) * 32 + lane];
#pragma unroll
                for (int mb = 0; mb < 2; mb++) {
                    mma16816(acc[mb][nb], ahi[mb], wh.x, wh.y);  // Ahi*Bhi
                    mma16816(acc[mb][nb], ahi[mb], wl.x, wl.y);  // Ahi*Blo
                    mma16816(acc[mb][nb], alo[mb], wh.x, wh.y);  // Alo*Bhi
                }
            }
        }
        __syncthreads();
    }

    // ---- Bias add ----
    int col0 = t * 2;
#pragma unroll
    for (int nb = 0; nb < 16; nb++) {
        float b0 = bs[nb * 8 + col0];
        float b1 = bs[nb * 8 + col0 + 1];
#pragma unroll
        for (int mb = 0; mb < 2; mb++) {
            acc[mb][nb][0] += b0; acc[mb][nb][1] += b1;
            acc[mb][nb][2] += b0; acc[mb][nb][3] += b1;
        }
    }

    // ---- Softmax per row (warp-local: quad owns full 128-col row) ----
#pragma unroll
    for (int mb = 0; mb < 2; mb++) {
        float mxA = -3.4e38f, mxB = -3.4e38f;
#pragma unroll
        for (int nb = 0; nb < 16; nb++) {
            mxA = fmaxf(mxA, fmaxf(acc[mb][nb][0], acc[mb][nb][1]));
            mxB = fmaxf(mxB, fmaxf(acc[mb][nb][2], acc[mb][nb][3]));
        }
#pragma unroll
        for (int o = 1; o <= 2; o <<= 1) {
            mxA = fmaxf(mxA, __shfl_xor_sync(0xffffffffu, mxA, o));
            mxB = fmaxf(mxB, __shfl_xor_sync(0xffffffffu, mxB, o));
        }
        float sA = 0.0f, sB = 0.0f;
#pragma unroll
        for (int nb = 0; nb < 16; nb++) {
            acc[mb][nb][0] = __expf(acc[mb][nb][0] - mxA);
            acc[mb][nb][1] = __expf(acc[mb][nb][1] - mxA);
            acc[mb][nb][2] = __expf(acc[mb][nb][2] - mxB);
            acc[mb][nb][3] = __expf(acc[mb][nb][3] - mxB);
            sA += acc[mb][nb][0] + acc[mb][nb][1];
            sB += acc[mb][nb][2] + acc[mb][nb][3];
        }
#pragma unroll
        for (int o = 1; o <= 2; o <<= 1) {
            sA += __shfl_xor_sync(0xffffffffu, sA, o);
            sB += __shfl_xor_sync(0xffffffffu, sB, o);
        }
        float invA = 1.0f / sA, invB = 1.0f / sB;
#pragma unroll
        for (int nb = 0; nb < 16; nb++) {
            acc[mb][nb][0] *= invA; acc[mb][nb][1] *= invA;
            acc[mb][nb][2] *= invB; acc[mb][nb][3] *= invB;
        }
    }

    // ---- Inverted gather: write each row to every k in its bucket ----
#pragma unroll
    for (int mb = 0; mb < 2; mb++) {
        int rowA = wb + mb * 16 + q;
        {
            int p = p0 + rowA;
            int n = min(g_cnt[p], BCAP);
            for (int j = 0; j < n; j++) {
                int k = g_bucket[(size_t)p * BCAP + j];
                float2* o = (float2*)(out + (size_t)k * NCLS);
#pragma unroll
                for (int nb = 0; nb < 16; nb++)
                    o[nb * 4 + t] = make_float2(acc[mb][nb][0], acc[mb][nb][1]);
            }
        }
        {
            int p = p0 + rowA + 8;
            int n = min(g_cnt[p], BCAP);
            for (int j = 0; j < n; j++) {
                int k = g_bucket[(size_t)p * BCAP + j];
                float2* o = (float2*)(out + (size_t)k * NCLS);
#pragma unroll
                for (int nb = 0; nb < 16; nb++)
                    o[nb * 4 + t] = make_float2(acc[mb][nb][2], acc[mb][nb][3]);
            }
        }
    }
}

// ---------------------------------------------------------------------------
// Launch
// ---------------------------------------------------------------------------
extern "C" void kernel_launch(void* const* d_in, const int* in_sizes, int n_in,
                              void* d_out, int out_size) {
    const float* gc   = (const float*)d_in[0];   // [1,128,512,512] f32
    const void*  cmap = d_in[1];                 // [1,131072] int64/int32
    const float* Wc   = (const float*)d_in[2];   // [128,128] f32
    const float* bc   = (const float*)d_in[3];   // [128] f32
    float*       out  = (float*)d_out;           // [131072,128] f32

    zero_convert_kernel<<<HW / 256, 256>>>(cmap);
    scatter_kernel<<<K / 256, 256>>>();
    prepW_kernel<<<32, 256>>>(Wc);

    cudaFuncSetAttribute(gemm_kernel,
                         cudaFuncAttributeMaxDynamicSharedMemorySize, SM_TOTAL);
    gemm_kernel<<<NTILES, 128, SM_TOTAL>>>(gc, bc, out);
}